// round 14
// baseline (speedup 1.0000x reference)
#include <cuda_runtime.h>
#include <math.h>

#define HIDDEN 768
#define INTER 3072
#define HEADS 12
#define HEAD_DIM 256
#define BATCH 8
#define SEQ 4096
#define K3_CHUNKS 4
#define K3_COLS 192
#define K3_TROWS 64
#define K3_PITCH 196          /* 192 + 4 pad; 784B stride, bank-safe */
#define K3_SMEM_FLOATS (K3_TROWS * K3_PITCH + K3_COLS * HEADS)
#define K5_CHUNKS 64
#define K5_ROWS 64
#define NLOGITS (BATCH * HEADS * SEQ)

typedef unsigned long long u64;

// ---------------- f32x2 helpers (sm_103a packed FMA) ----------------
__device__ __forceinline__ u64 pack2(float lo, float hi) {
    u64 r;
    asm("mov.b64 %0, {%1, %2};" : "=l"(r)
        : "r"(__float_as_uint(lo)), "r"(__float_as_uint(hi)));
    return r;
}
__device__ __forceinline__ void fma2(u64& d, u64 a, u64 b) {
    asm("fma.rn.f32x2 %0, %1, %2, %0;" : "+l"(d) : "l"(a), "l"(b));
}
__device__ __forceinline__ float2 unpack2(u64 v) {
    unsigned lo, hi;
    asm("mov.b64 {%0, %1}, %2;" : "=r"(lo), "=r"(hi) : "l"(v));
    return make_float2(__uint_as_float(lo), __uint_as_float(hi));
}

// ---------------- scratch (static device globals; no allocation) ----------------
__device__ float g_q1[24 * INTER];         // q partials per c-chunk
__device__ float g_q[INTER];               // scaled q [h][d]
__device__ float g_wk[HIDDEN * HEADS];     // folded key weights [c][h]
__device__ float g_logits[NLOGITS];        // logits (atomic-accumulated by k3)
__device__ float g_pp[BATCH * K5_CHUNKS * HEADS * HIDDEN]; // pool partials (18.9 MB)
__device__ float g_ctx[BATCH * INTER];
__device__ float g_out[BATCH * HIDDEN];    // pre-LN output

// ---------------- K1: q partials + zero g_logits ------------------------------
__global__ __launch_bounds__(256) void k1_qpart(const float* __restrict__ pq,
                                                const float* __restrict__ Wq) {
    int gid = blockIdx.x * 256 + threadIdx.x;       // 288*256 = 73728 threads
    for (int i = gid; i < NLOGITS; i += 288 * 256) g_logits[i] = 0.0f;

    int cc = blockIdx.x / 12;                       // 0..23
    int colc = blockIdx.x % 12;                     // 0..11
    int c0 = cc * 32;
    __shared__ float sq[32];
    if (threadIdx.x < 32) sq[threadIdx.x] = pq[c0 + threadIdx.x];
    __syncthreads();
    int col = colc * 256 + threadIdx.x;
    float acc = 0.0f;
#pragma unroll 8
    for (int c = 0; c < 32; c++)
        acc += sq[c] * Wq[(size_t)(c0 + c) * INTER + col];
    g_q1[cc * INTER + col] = acc;
}

// ---------------- K1b: reduce partials + bq, scale by softplus ------------------
__global__ void k1b_qscale(const float* __restrict__ pds,
                           const float* __restrict__ bq) {
    int i = blockIdx.x * 256 + threadIdx.x;         // grid 12*256 = 3072
    float s = bq[i];
#pragma unroll
    for (int cc = 0; cc < 24; cc++) s += g_q1[cc * INTER + i];
    float x = pds[threadIdx.x];                     // HEAD_DIM == 256
    float sp = (x > 20.0f) ? x : log1pf(expf(x));
    const float scale = 1.442695041f / 16.0f;       // r_softplus_0 / sqrt(HEAD_DIM)
    g_q[i] = s * scale * sp;
}

// ---------------- K2: fold wk[c][h] = Wk[c, h*256+:] . q[h,:] -------------------
// warp-per-(c,h): 9216 dot products. grid 1152 x 256. (q.bk dropped: softmax-invariant)
__global__ __launch_bounds__(256) void k2_fold(const float* __restrict__ Wk) {
    int p = blockIdx.x * 8 + (threadIdx.x >> 5);
    int lane = threadIdx.x & 31;
    int c = p / HEADS;
    int h = p - c * HEADS;
    const float* wrow = Wk + (size_t)c * INTER + h * HEAD_DIM;
    const float* qrow = g_q + h * HEAD_DIM;
    float s = 0.0f;
#pragma unroll
    for (int j = 0; j < HEAD_DIM; j += 32) s += wrow[j + lane] * qrow[j + lane];
#pragma unroll
    for (int o = 16; o; o >>= 1) s += __shfl_xor_sync(0xffffffffu, s, o);
    if (!lane) g_wk[p] = s;
}

// ---------------- K3: logit partials; 64-row tiles (R9 shape), atomic output ----
// grid = 512 rowblocks x 4 chunks = 2048; block 256; dynamic smem 58 KB.
__global__ __launch_bounds__(256) void k3_logits(const float* __restrict__ hidden) {
    extern __shared__ __align__(16) float dsm[];
    float* s_h  = dsm;                               // 64*196 = 12544 floats
    float* s_wk = dsm + K3_TROWS * K3_PITCH;         // 192*12 = 2304 floats
    float* s_red = dsm;                              // aliased after compute (6144)
    int chunk = blockIdx.x & 3;
    int rowblk = blockIdx.x >> 2;
    int row0 = rowblk * K3_TROWS;
    int tid = threadIdx.x;

    for (int i = tid; i < K3_COLS * HEADS; i += 256)
        s_wk[i] = g_wk[chunk * K3_COLS * HEADS + i];

    // stage 64 rows x 192 cols: r = tid>>2, sub = tid&3; 12 float4 each
    {
        int r = tid >> 2, sub = tid & 3;
        const float4* src = (const float4*)(hidden + (size_t)(row0 + r) * HIDDEN
                                            + chunk * K3_COLS);
        float4* dst = (float4*)(s_h + r * K3_PITCH);
#pragma unroll
        for (int j = 0; j < 12; j++)
            dst[sub + 4 * j] = src[sub + 4 * j];
    }
    __syncthreads();

    int w = tid >> 5, lane = tid & 31;
    const float* h0 = s_h + lane * K3_PITCH + w * 24;
    const float* h1 = h0 + 32 * K3_PITCH;
    const float* wks = s_wk + (w * 24) * HEADS;

    u64 acc0[6], acc1[6];
#pragma unroll
    for (int k = 0; k < 6; k++) { acc0[k] = 0ull; acc1[k] = 0ull; }

#pragma unroll
    for (int i = 0; i < 6; i++) {                   // 6 float4 = 24 cols
        float4 va = *(const float4*)(h0 + 4 * i);
        float4 vb = *(const float4*)(h1 + 4 * i);
        const ulonglong2* w2 = (const ulonglong2*)(wks + (4 * i) * HEADS);
        float aa[4] = {va.x, va.y, va.z, va.w};
        float bb[4] = {vb.x, vb.y, vb.z, vb.w};
#pragma unroll
        for (int j = 0; j < 4; j++) {
            ulonglong2 wa = w2[j * 3 + 0];
            ulonglong2 wb = w2[j * 3 + 1];
            ulonglong2 wc = w2[j * 3 + 2];
            u64 fa = pack2(aa[j], aa[j]);
            u64 fb = pack2(bb[j], bb[j]);
            fma2(acc0[0], fa, wa.x);
            fma2(acc0[1], fa, wa.y);
            fma2(acc0[2], fa, wb.x);
            fma2(acc0[3], fa, wb.y);
            fma2(acc0[4], fa, wc.x);
            fma2(acc0[5], fa, wc.y);
            fma2(acc1[0], fb, wa.x);
            fma2(acc1[1], fb, wa.y);
            fma2(acc1[2], fb, wb.x);
            fma2(acc1[3], fb, wb.y);
            fma2(acc1[4], fb, wc.x);
            fma2(acc1[5], fb, wc.y);
        }
    }
    __syncthreads();                                // all s_h reads done (aliasing)
    // per-warp partials -> s_red [w][row][head]
    {
        float* rp0 = s_red + (w * K3_TROWS + lane) * HEADS;
        float* rp1 = s_red + (w * K3_TROWS + lane + 32) * HEADS;
#pragma unroll
        for (int k = 0; k < 6; k++) {
            float2 p0 = unpack2(acc0[k]);
            float2 p1 = unpack2(acc1[k]);
            rp0[2 * k] = p0.x; rp0[2 * k + 1] = p0.y;
            rp1[2 * k] = p1.x; rp1[2 * k + 1] = p1.y;
        }
    }
    __syncthreads();
    // final reduce over 8 warps: 768 outputs, strided; atomic into g_logits
    for (int o = tid; o < K3_TROWS * HEADS; o += 256) {
        int rr = o / HEADS, h = o - rr * HEADS;
        float s = 0.0f;
#pragma unroll
        for (int ww = 0; ww < 8; ww++)
            s += s_red[(ww * K3_TROWS + rr) * HEADS + h];
        int grow = row0 + rr;
        int b = grow >> 12;
        int sq = grow & (SEQ - 1);
        atomicAdd(&g_logits[((size_t)(b * HEADS + h)) * SEQ + sq], s);
    }
}

// ---------------- K4: softmax over s per (b,h); 1024 thr for latency hiding -----
__global__ __launch_bounds__(1024) void k4_softmax(float* __restrict__ out_attn,
                                                   const float* __restrict__ bv,
                                                   const float* __restrict__ bp) {
    int gid = blockIdx.x * 1024 + threadIdx.x;      // grid 96 x 1024
    if (gid < BATCH * INTER) g_ctx[gid] = bv[gid % INTER];
    if (gid < BATCH * HIDDEN) g_out[gid] = bp[gid % HIDDEN];

    __shared__ float sv[SEQ];                       // 16 KB
    __shared__ float red[32];
    __shared__ float sbc;
    int bh = blockIdx.x;
    int tid = threadIdx.x, lane = tid & 31, wid = tid >> 5;
    size_t base = (size_t)bh * SEQ;

    float mx = -3.4e38f;
#pragma unroll
    for (int i = tid; i < SEQ; i += 1024) {
        float v = g_logits[base + i];
        sv[i] = v; mx = fmaxf(mx, v);
    }
#pragma unroll
    for (int o = 16; o; o >>= 1) mx = fmaxf(mx, __shfl_xor_sync(0xffffffffu, mx, o));
    if (!lane) red[wid] = mx;
    __syncthreads();
    if (tid == 0) { float m = red[0]; for (int w = 1; w < 32; w++) m = fmaxf(m, red[w]); sbc = m; }
    __syncthreads();
    float m = sbc;

    float sum = 0.0f;
#pragma unroll
    for (int i = tid; i < SEQ; i += 1024) { float e = __expf(sv[i] - m); sv[i] = e; sum += e; }
#pragma unroll
    for (int o = 16; o; o >>= 1) sum += __shfl_xor_sync(0xffffffffu, sum, o);
    if (!lane) red[wid] = sum;
    __syncthreads();
    if (tid == 0) { float s = 0; for (int w = 0; w < 32; w++) s += red[w]; sbc = 1.0f / s; }
    __syncthreads();
    float inv = sbc;
#pragma unroll
    for (int i = tid; i < SEQ; i += 1024) out_attn[base + i] = sv[i] * inv;
}

// ---------------- K5: partial p[b,h,c] = sum_s attn * hidden (pass C) -----------
// grid = 8 b x 64 chunks = 512; block 384 (12 warps); thread owns 2 floats.
// Halved accumulator state (24 regs) -> 3 blocks/SM = 36 warps for latency hiding.
__global__ __launch_bounds__(384) void k5_pool(const float* __restrict__ hidden,
                                               const float* __restrict__ attn) {
    __shared__ __align__(16) float s_a[K5_ROWS * HEADS]; // [r][h], 3 KB
    int b = blockIdx.x >> 6;
    int s0 = (blockIdx.x & (K5_CHUNKS - 1)) * K5_ROWS;
    for (int i = threadIdx.x; i < K5_ROWS * HEADS; i += 384) {
        int h = i / K5_ROWS, r = i - h * K5_ROWS;   // coalesced attn reads
        s_a[r * HEADS + h] = attn[((size_t)(b * HEADS + h)) * SEQ + s0 + r];
    }
    __syncthreads();

    int c0 = threadIdx.x * 2;                       // 384*2 = 768
    const float2* hp = (const float2*)(hidden + ((size_t)b * SEQ + s0) * HIDDEN)
                     + threadIdx.x;

    u64 acc[6][2];                                  // [head-pair][col]
#pragma unroll
    for (int k = 0; k < 6; k++) { acc[k][0] = 0ull; acc[k][1] = 0ull; }

#pragma unroll 8
    for (int r = 0; r < K5_ROWS; r++) {
        float2 hv = hp[(size_t)r * (HIDDEN / 2)];
        u64 hx = pack2(hv.x, hv.x);
        u64 hy = pack2(hv.y, hv.y);
        const ulonglong2* ap = (const ulonglong2*)(s_a + r * HEADS);
        ulonglong2 a0 = ap[0], a1 = ap[1], a2 = ap[2];
        u64 av[6] = {a0.x, a0.y, a1.x, a1.y, a2.x, a2.y};
#pragma unroll
        for (int k = 0; k < 6; k++) {
            fma2(acc[k][0], av[k], hx);
            fma2(acc[k][1], av[k], hy);
        }
    }
    float* pp = g_pp + (size_t)blockIdx.x * (HEADS * HIDDEN);
#pragma unroll
    for (int k = 0; k < 6; k++) {
        float2 p0 = unpack2(acc[k][0]);             // (head 2k, 2k+1) col c0
        float2 p1 = unpack2(acc[k][1]);             // (head 2k, 2k+1) col c0+1
        *(float2*)(pp + (2 * k) * HIDDEN + c0)     = make_float2(p0.x, p1.x);
        *(float2*)(pp + (2 * k + 1) * HIDDEN + c0) = make_float2(p0.y, p1.y);
    }
}

// ---------------- K6a: ctx = (chunk-reduced p) @ Wv cols + bv (atomic over c) ---
__global__ __launch_bounds__(256) void k6a_ctx(const float* __restrict__ Wv) {
    int h = blockIdx.x >> 4;                        // grid 12*16
    int c0 = (blockIdx.x & 15) * 48;
    __shared__ float sp[BATCH][48];
    for (int i = threadIdx.x; i < BATCH * 48; i += 256) {
        int b = i / 48, c = i - b * 48;
        const float* src = g_pp + (size_t)(b * K5_CHUNKS) * (HEADS * HIDDEN)
                         + h * HIDDEN + c0 + c;
        float s = 0.0f;
#pragma unroll 8
        for (int ch = 0; ch < K5_CHUNKS; ch++)
            s += src[(size_t)ch * (HEADS * HIDDEN)];
        sp[b][c] = s;
    }
    __syncthreads();
    int col = h * HEAD_DIM + threadIdx.x;
    float acc[BATCH];
#pragma unroll
    for (int b = 0; b < BATCH; b++) acc[b] = 0.0f;
#pragma unroll 4
    for (int c = 0; c < 48; c++) {
        float w = Wv[(size_t)(c0 + c) * INTER + col];
#pragma unroll
        for (int b = 0; b < BATCH; b++) acc[b] += sp[b][c] * w;
    }
#pragma unroll
    for (int b = 0; b < BATCH; b++) atomicAdd(&g_ctx[b * INTER + col], acc[b]);
}

// ---------------- K6b: out[b,j] = ctx[b,:].Wp col + bp (atomic over i) -----------
__global__ __launch_bounds__(256) void k6b_out(const float* __restrict__ Wp) {
    int ic = blockIdx.x / 3;                        // grid 48*3
    int jt = blockIdx.x % 3;
    int i0 = ic * 64;
    __shared__ float sc[BATCH][64];
    for (int i = threadIdx.x; i < BATCH * 64; i += 256) {
        int b = i / 64, ii = i - b * 64;
        sc[b][ii] = g_ctx[b * INTER + i0 + ii];
    }
    __syncthreads();
    int j = jt * 256 + threadIdx.x;
    float acc[BATCH];
#pragma unroll
    for (int b = 0; b < BATCH; b++) acc[b] = 0.0f;
#pragma unroll 4
    for (int ii = 0; ii < 64; ii++) {
        float w = Wp[(size_t)(i0 + ii) * HIDDEN + j];
#pragma unroll
        for (int b = 0; b < BATCH; b++) acc[b] += sc[b][ii] * w;
    }
#pragma unroll
    for (int b = 0; b < BATCH; b++) atomicAdd(&g_out[b * HIDDEN + j], acc[b]);
}

// ---------------- K7: layernorm per batch row -> pooled output -------------------
__global__ __launch_bounds__(256) void k7_ln(float* __restrict__ pooled,
                                             const float* __restrict__ lnw,
                                             const float* __restrict__ lnb) {
    int b = blockIdx.x, tid = threadIdx.x, lane = tid & 31, wid = tid >> 5;
    __shared__ float sx[HIDDEN];
    __shared__ float red[8];
    __shared__ float sm, sr;
    float loc = 0.0f;
    for (int i = tid; i < HIDDEN; i += 256) { float x = g_out[b * HIDDEN + i]; sx[i] = x; loc += x; }
#pragma unroll
    for (int o = 16; o; o >>= 1) loc += __shfl_xor_sync(0xffffffffu, loc, o);
    if (!lane) red[wid] = loc;
    __syncthreads();
    if (tid == 0) { float s = 0; for (int w = 0; w < 8; w++) s += red[w]; sm = s / HIDDEN; }
    __syncthreads();
    float mean = sm;
    loc = 0.0f;
    for (int i = tid; i < HIDDEN; i += 256) { float d = sx[i] - mean; loc += d * d; }
#pragma unroll
    for (int o = 16; o; o >>= 1) loc += __shfl_xor_sync(0xffffffffu, loc, o);
    if (!lane) red[wid] = loc;
    __syncthreads();
    if (tid == 0) { float s = 0; for (int w = 0; w < 8; w++) s += red[w]; sr = rsqrtf(s / HIDDEN + 1e-6f); }
    __syncthreads();
    float rstd = sr;
    for (int i = tid; i < HIDDEN; i += 256)
        pooled[b * HIDDEN + i] = (sx[i] - mean) * rstd * (lnw[i] + 1.0f) + lnb[i];
}

// ---------------- launch -----------------------------------------------------------
extern "C" void kernel_launch(void* const* d_in, const int* in_sizes, int n_in,
                              void* d_out, int out_size) {
    const float* hidden = (const float*)d_in[0];
    const float* pq     = (const float*)d_in[1];
    const float* Wq     = (const float*)d_in[2];
    const float* bq     = (const float*)d_in[3];
    const float* Wk     = (const float*)d_in[4];
    const float* Wv     = (const float*)d_in[6];
    const float* bv     = (const float*)d_in[7];
    const float* Wp     = (const float*)d_in[8];
    const float* bp     = (const float*)d_in[9];
    const float* pds    = (const float*)d_in[10];
    const float* lnw    = (const float*)d_in[11];
    const float* lnb    = (const float*)d_in[12];

    float* pooled   = (float*)d_out;                       // [8,1,768]
    float* out_attn = (float*)d_out + BATCH * HIDDEN;      // [8,12,1,4096]

    const int k3_smem = K3_SMEM_FLOATS * sizeof(float);    // 59392 B
    static int s_attr_done = 0;
    if (!s_attr_done) {
        cudaFuncSetAttribute(k3_logits, cudaFuncAttributeMaxDynamicSharedMemorySize,
                             k3_smem);
        s_attr_done = 1;
    }

    k1_qpart  <<<288, 256>>>(pq, Wq);
    k1b_qscale<<<12, 256>>>(pds, bq);
    k2_fold   <<<1152, 256>>>(Wk);
    k3_logits <<<2048, 256, k3_smem>>>(hidden);
    k4_softmax<<<96, 1024>>>(out_attn, bv, bp);
    k5_pool   <<<512, 384>>>(hidden, out_attn);
    k6a_ctx   <<<192, 256>>>(Wv);
    k6b_out   <<<144, 256>>>(Wp);
    k7_ln     <<<8, 256>>>(pooled, lnw, lnb);
}

// round 15
// speedup vs baseline: 1.2951x; 1.2951x over previous
#include <cuda_runtime.h>
#include <math.h>

#define HIDDEN 768
#define INTER 3072
#define HEADS 12
#define HEAD_DIM 256
#define BATCH 8
#define SEQ 4096
#define K3_CHUNKS 4
#define K3_COLS 192
#define K3_TROWS 64
#define K3_PITCH 196          /* 192 + 4 pad; 784B stride, bank-safe */
#define K3_SMEM_FLOATS (K3_TROWS * K3_PITCH + K3_COLS * HEADS)
#define K5_CHUNKS 64
#define K5_ROWS 64
#define NLOGITS (BATCH * HEADS * SEQ)

typedef unsigned long long u64;

// ---------------- f32x2 helpers (sm_103a packed FMA) ----------------
__device__ __forceinline__ u64 pack2(float lo, float hi) {
    u64 r;
    asm("mov.b64 %0, {%1, %2};" : "=l"(r)
        : "r"(__float_as_uint(lo)), "r"(__float_as_uint(hi)));
    return r;
}
__device__ __forceinline__ void fma2(u64& d, u64 a, u64 b) {
    asm("fma.rn.f32x2 %0, %1, %2, %0;" : "+l"(d) : "l"(a), "l"(b));
}
__device__ __forceinline__ float2 unpack2(u64 v) {
    unsigned lo, hi;
    asm("mov.b64 {%0, %1}, %2;" : "=r"(lo), "=r"(hi) : "l"(v));
    return make_float2(__uint_as_float(lo), __uint_as_float(hi));
}

// ---------------- scratch (static device globals; no allocation) ----------------
__device__ float g_q1[24 * INTER];         // q partials per c-chunk
__device__ float g_q[INTER];               // scaled q [h][d]
__device__ float g_wk[HIDDEN * HEADS];     // folded key weights [c][h]
__device__ float g_logits[NLOGITS];        // logits (atomic-accumulated by k3)
__device__ float g_pp[BATCH * K5_CHUNKS * HEADS * HIDDEN]; // pool partials (18.9 MB)
__device__ float g_ctx[BATCH * INTER];
__device__ float g_out[BATCH * HIDDEN];    // pre-LN output

// ---------------- K1: q partials + zero g_logits ------------------------------
__global__ __launch_bounds__(256) void k1_qpart(const float* __restrict__ pq,
                                                const float* __restrict__ Wq) {
    int gid = blockIdx.x * 256 + threadIdx.x;       // 288*256 = 73728 threads
    for (int i = gid; i < NLOGITS; i += 288 * 256) g_logits[i] = 0.0f;

    int cc = blockIdx.x / 12;                       // 0..23
    int colc = blockIdx.x % 12;                     // 0..11
    int c0 = cc * 32;
    __shared__ float sq[32];
    if (threadIdx.x < 32) sq[threadIdx.x] = pq[c0 + threadIdx.x];
    __syncthreads();
    int col = colc * 256 + threadIdx.x;
    float acc = 0.0f;
#pragma unroll 8
    for (int c = 0; c < 32; c++)
        acc += sq[c] * Wq[(size_t)(c0 + c) * INTER + col];
    g_q1[cc * INTER + col] = acc;
}

// ---------------- K1b: reduce partials + bq, scale by softplus ------------------
__global__ void k1b_qscale(const float* __restrict__ pds,
                           const float* __restrict__ bq) {
    int i = blockIdx.x * 256 + threadIdx.x;         // grid 12*256 = 3072
    float s = bq[i];
#pragma unroll
    for (int cc = 0; cc < 24; cc++) s += g_q1[cc * INTER + i];
    float x = pds[threadIdx.x];                     // HEAD_DIM == 256
    float sp = (x > 20.0f) ? x : log1pf(expf(x));
    const float scale = 1.442695041f / 16.0f;       // r_softplus_0 / sqrt(HEAD_DIM)
    g_q[i] = s * scale * sp;
}

// ---------------- K2: fold wk[c][h] = Wk[c, h*256+:] . q[h,:] -------------------
// warp-per-(c,h): 9216 dot products. grid 1152 x 256. (q.bk dropped: softmax-invariant)
__global__ __launch_bounds__(256) void k2_fold(const float* __restrict__ Wk) {
    int p = blockIdx.x * 8 + (threadIdx.x >> 5);
    int lane = threadIdx.x & 31;
    int c = p / HEADS;
    int h = p - c * HEADS;
    const float* wrow = Wk + (size_t)c * INTER + h * HEAD_DIM;
    const float* qrow = g_q + h * HEAD_DIM;
    float s = 0.0f;
#pragma unroll
    for (int j = 0; j < HEAD_DIM; j += 32) s += wrow[j + lane] * qrow[j + lane];
#pragma unroll
    for (int o = 16; o; o >>= 1) s += __shfl_xor_sync(0xffffffffu, s, o);
    if (!lane) g_wk[p] = s;
}

// ---------------- K3: logit partials; 64-row tiles (R9 shape), atomic output ----
// grid = 512 rowblocks x 4 chunks = 2048; block 256; dynamic smem 58 KB.
__global__ __launch_bounds__(256) void k3_logits(const float* __restrict__ hidden) {
    extern __shared__ __align__(16) float dsm[];
    float* s_h  = dsm;                               // 64*196 = 12544 floats
    float* s_wk = dsm + K3_TROWS * K3_PITCH;         // 192*12 = 2304 floats
    float* s_red = dsm;                              // aliased after compute (6144)
    int chunk = blockIdx.x & 3;
    int rowblk = blockIdx.x >> 2;
    int row0 = rowblk * K3_TROWS;
    int tid = threadIdx.x;

    for (int i = tid; i < K3_COLS * HEADS; i += 256)
        s_wk[i] = g_wk[chunk * K3_COLS * HEADS + i];

    // stage 64 rows x 192 cols: r = tid>>2, sub = tid&3; 12 float4 each
    {
        int r = tid >> 2, sub = tid & 3;
        const float4* src = (const float4*)(hidden + (size_t)(row0 + r) * HIDDEN
                                            + chunk * K3_COLS);
        float4* dst = (float4*)(s_h + r * K3_PITCH);
#pragma unroll
        for (int j = 0; j < 12; j++)
            dst[sub + 4 * j] = src[sub + 4 * j];
    }
    __syncthreads();

    int w = tid >> 5, lane = tid & 31;
    const float* h0 = s_h + lane * K3_PITCH + w * 24;
    const float* h1 = h0 + 32 * K3_PITCH;
    const float* wks = s_wk + (w * 24) * HEADS;

    u64 acc0[6], acc1[6];
#pragma unroll
    for (int k = 0; k < 6; k++) { acc0[k] = 0ull; acc1[k] = 0ull; }

#pragma unroll
    for (int i = 0; i < 6; i++) {                   // 6 float4 = 24 cols
        float4 va = *(const float4*)(h0 + 4 * i);
        float4 vb = *(const float4*)(h1 + 4 * i);
        const ulonglong2* w2 = (const ulonglong2*)(wks + (4 * i) * HEADS);
        float aa[4] = {va.x, va.y, va.z, va.w};
        float bb[4] = {vb.x, vb.y, vb.z, vb.w};
#pragma unroll
        for (int j = 0; j < 4; j++) {
            ulonglong2 wa = w2[j * 3 + 0];
            ulonglong2 wb = w2[j * 3 + 1];
            ulonglong2 wc = w2[j * 3 + 2];
            u64 fa = pack2(aa[j], aa[j]);
            u64 fb = pack2(bb[j], bb[j]);
            fma2(acc0[0], fa, wa.x);
            fma2(acc0[1], fa, wa.y);
            fma2(acc0[2], fa, wb.x);
            fma2(acc0[3], fa, wb.y);
            fma2(acc0[4], fa, wc.x);
            fma2(acc0[5], fa, wc.y);
            fma2(acc1[0], fb, wa.x);
            fma2(acc1[1], fb, wa.y);
            fma2(acc1[2], fb, wb.x);
            fma2(acc1[3], fb, wb.y);
            fma2(acc1[4], fb, wc.x);
            fma2(acc1[5], fb, wc.y);
        }
    }
    __syncthreads();                                // all s_h reads done (aliasing)
    // per-warp partials -> s_red [w][row][head]
    {
        float* rp0 = s_red + (w * K3_TROWS + lane) * HEADS;
        float* rp1 = s_red + (w * K3_TROWS + lane + 32) * HEADS;
#pragma unroll
        for (int k = 0; k < 6; k++) {
            float2 p0 = unpack2(acc0[k]);
            float2 p1 = unpack2(acc1[k]);
            rp0[2 * k] = p0.x; rp0[2 * k + 1] = p0.y;
            rp1[2 * k] = p1.x; rp1[2 * k + 1] = p1.y;
        }
    }
    __syncthreads();
    // final reduce over 8 warps: 768 outputs, strided; atomic into g_logits
    for (int o = tid; o < K3_TROWS * HEADS; o += 256) {
        int rr = o / HEADS, h = o - rr * HEADS;
        float s = 0.0f;
#pragma unroll
        for (int ww = 0; ww < 8; ww++)
            s += s_red[(ww * K3_TROWS + rr) * HEADS + h];
        int grow = row0 + rr;
        int b = grow >> 12;
        int sq = grow & (SEQ - 1);
        atomicAdd(&g_logits[((size_t)(b * HEADS + h)) * SEQ + sq], s);
    }
}

// ---------------- K4: softmax over s per (b,h); 1024 thr for latency hiding -----
__global__ __launch_bounds__(1024) void k4_softmax(float* __restrict__ out_attn,
                                                   const float* __restrict__ bv,
                                                   const float* __restrict__ bp) {
    int gid = blockIdx.x * 1024 + threadIdx.x;      // grid 96 x 1024
    if (gid < BATCH * INTER) g_ctx[gid] = bv[gid % INTER];
    if (gid < BATCH * HIDDEN) g_out[gid] = bp[gid % HIDDEN];

    __shared__ float sv[SEQ];                       // 16 KB
    __shared__ float red[32];
    __shared__ float sbc;
    int bh = blockIdx.x;
    int tid = threadIdx.x, lane = tid & 31, wid = tid >> 5;
    size_t base = (size_t)bh * SEQ;

    float mx = -3.4e38f;
#pragma unroll
    for (int i = tid; i < SEQ; i += 1024) {
        float v = g_logits[base + i];
        sv[i] = v; mx = fmaxf(mx, v);
    }
#pragma unroll
    for (int o = 16; o; o >>= 1) mx = fmaxf(mx, __shfl_xor_sync(0xffffffffu, mx, o));
    if (!lane) red[wid] = mx;
    __syncthreads();
    if (tid == 0) { float m = red[0]; for (int w = 1; w < 32; w++) m = fmaxf(m, red[w]); sbc = m; }
    __syncthreads();
    float m = sbc;

    float sum = 0.0f;
#pragma unroll
    for (int i = tid; i < SEQ; i += 1024) { float e = __expf(sv[i] - m); sv[i] = e; sum += e; }
#pragma unroll
    for (int o = 16; o; o >>= 1) sum += __shfl_xor_sync(0xffffffffu, sum, o);
    if (!lane) red[wid] = sum;
    __syncthreads();
    if (tid == 0) { float s = 0; for (int w = 0; w < 32; w++) s += red[w]; sbc = 1.0f / s; }
    __syncthreads();
    float inv = sbc;
#pragma unroll
    for (int i = tid; i < SEQ; i += 1024) out_attn[base + i] = sv[i] * inv;
}

// ---------------- K5: partial p[b,h,c] = sum_s attn * hidden (pass C) -----------
// grid = 8 b x 64 chunks = 512; 64 rows/chunk; head-paired f32x2.
__global__ __launch_bounds__(192) void k5_pool(const float* __restrict__ hidden,
                                               const float* __restrict__ attn) {
    __shared__ __align__(16) float s_a[K5_ROWS * HEADS]; // [r][h], 3 KB
    int b = blockIdx.x >> 6;
    int s0 = (blockIdx.x & (K5_CHUNKS - 1)) * K5_ROWS;
    for (int i = threadIdx.x; i < K5_ROWS * HEADS; i += 192) {
        int h = i / K5_ROWS, r = i - h * K5_ROWS;   // coalesced attn reads
        s_a[r * HEADS + h] = attn[((size_t)(b * HEADS + h)) * SEQ + s0 + r];
    }
    __syncthreads();

    int c0 = threadIdx.x * 4;                       // 192*4 = 768
    const float4* hp = (const float4*)(hidden + ((size_t)b * SEQ + s0) * HIDDEN + c0);

    u64 acc[6][4];                                  // [head-pair][col]
#pragma unroll
    for (int k = 0; k < 6; k++)
#pragma unroll
        for (int c = 0; c < 4; c++) acc[k][c] = 0ull;

#pragma unroll 4
    for (int r = 0; r < K5_ROWS; r++) {
        float4 hv = hp[(size_t)r * (HIDDEN / 4)];
        u64 hx = pack2(hv.x, hv.x);
        u64 hy = pack2(hv.y, hv.y);
        u64 hz = pack2(hv.z, hv.z);
        u64 hw = pack2(hv.w, hv.w);
        const ulonglong2* ap = (const ulonglong2*)(s_a + r * HEADS);
        ulonglong2 a0 = ap[0], a1 = ap[1], a2 = ap[2];
        u64 av[6] = {a0.x, a0.y, a1.x, a1.y, a2.x, a2.y};
#pragma unroll
        for (int k = 0; k < 6; k++) {
            fma2(acc[k][0], av[k], hx);
            fma2(acc[k][1], av[k], hy);
            fma2(acc[k][2], av[k], hz);
            fma2(acc[k][3], av[k], hw);
        }
    }
    float* pp = g_pp + (size_t)blockIdx.x * (HEADS * HIDDEN);
#pragma unroll
    for (int k = 0; k < 6; k++) {
        float2 p0 = unpack2(acc[k][0]);
        float2 p1 = unpack2(acc[k][1]);
        float2 p2 = unpack2(acc[k][2]);
        float2 p3 = unpack2(acc[k][3]);
        *(float4*)(pp + (2 * k) * HIDDEN + c0)     = make_float4(p0.x, p1.x, p2.x, p3.x);
        *(float4*)(pp + (2 * k + 1) * HIDDEN + c0) = make_float4(p0.y, p1.y, p2.y, p3.y);
    }
}

// ---------------- K6a: ctx = (chunk-reduced p) @ Wv cols + bv (atomic over c) ---
__global__ __launch_bounds__(256) void k6a_ctx(const float* __restrict__ Wv) {
    int h = blockIdx.x >> 4;                        // grid 12*16
    int c0 = (blockIdx.x & 15) * 48;
    __shared__ float sp[BATCH][48];
    for (int i = threadIdx.x; i < BATCH * 48; i += 256) {
        int b = i / 48, c = i - b * 48;
        const float* src = g_pp + (size_t)(b * K5_CHUNKS) * (HEADS * HIDDEN)
                         + h * HIDDEN + c0 + c;
        float s = 0.0f;
#pragma unroll 8
        for (int ch = 0; ch < K5_CHUNKS; ch++)
            s += src[(size_t)ch * (HEADS * HIDDEN)];
        sp[b][c] = s;
    }
    __syncthreads();
    int col = h * HEAD_DIM + threadIdx.x;
    float acc[BATCH];
#pragma unroll
    for (int b = 0; b < BATCH; b++) acc[b] = 0.0f;
#pragma unroll 4
    for (int c = 0; c < 48; c++) {
        float w = Wv[(size_t)(c0 + c) * INTER + col];
#pragma unroll
        for (int b = 0; b < BATCH; b++) acc[b] += sp[b][c] * w;
    }
#pragma unroll
    for (int b = 0; b < BATCH; b++) atomicAdd(&g_ctx[b * INTER + col], acc[b]);
}

// ---------------- K6b: out[b,j] = ctx[b,:].Wp col + bp (atomic over i) -----------
__global__ __launch_bounds__(256) void k6b_out(const float* __restrict__ Wp) {
    int ic = blockIdx.x / 3;                        // grid 48*3
    int jt = blockIdx.x % 3;
    int i0 = ic * 64;
    __shared__ float sc[BATCH][64];
    for (int i = threadIdx.x; i < BATCH * 64; i += 256) {
        int b = i / 64, ii = i - b * 64;
        sc[b][ii] = g_ctx[b * INTER + i0 + ii];
    }
    __syncthreads();
    int j = jt * 256 + threadIdx.x;
    float acc[BATCH];
#pragma unroll
    for (int b = 0; b < BATCH; b++) acc[b] = 0.0f;
#pragma unroll 4
    for (int ii = 0; ii < 64; ii++) {
        float w = Wp[(size_t)(i0 + ii) * HIDDEN + j];
#pragma unroll
        for (int b = 0; b < BATCH; b++) acc[b] += sc[b][ii] * w;
    }
#pragma unroll
    for (int b = 0; b < BATCH; b++) atomicAdd(&g_out[b * HIDDEN + j], acc[b]);
}

// ---------------- K7: layernorm per batch row -> pooled output -------------------
__global__ __launch_bounds__(256) void k7_ln(float* __restrict__ pooled,
                                             const float* __restrict__ lnw,
                                             const float* __restrict__ lnb) {
    int b = blockIdx.x, tid = threadIdx.x, lane = tid & 31, wid = tid >> 5;
    __shared__ float sx[HIDDEN];
    __shared__ float red[8];
    __shared__ float sm, sr;
    float loc = 0.0f;
    for (int i = tid; i < HIDDEN; i += 256) { float x = g_out[b * HIDDEN + i]; sx[i] = x; loc += x; }
#pragma unroll
    for (int o = 16; o; o >>= 1) loc += __shfl_xor_sync(0xffffffffu, loc, o);
    if (!lane) red[wid] = loc;
    __syncthreads();
    if (tid == 0) { float s = 0; for (int w = 0; w < 8; w++) s += red[w]; sm = s / HIDDEN; }
    __syncthreads();
    float mean = sm;
    loc = 0.0f;
    for (int i = tid; i < HIDDEN; i += 256) { float d = sx[i] - mean; loc += d * d; }
#pragma unroll
    for (int o = 16; o; o >>= 1) loc += __shfl_xor_sync(0xffffffffu, loc, o);
    if (!lane) red[wid] = loc;
    __syncthreads();
    if (tid == 0) { float s = 0; for (int w = 0; w < 8; w++) s += red[w]; sr = rsqrtf(s / HIDDEN + 1e-6f); }
    __syncthreads();
    float rstd = sr;
    for (int i = tid; i < HIDDEN; i += 256)
        pooled[b * HIDDEN + i] = (sx[i] - mean) * rstd * (lnw[i] + 1.0f) + lnb[i];
}

// ---------------- launch -----------------------------------------------------------
extern "C" void kernel_launch(void* const* d_in, const int* in_sizes, int n_in,
                              void* d_out, int out_size) {
    const float* hidden = (const float*)d_in[0];
    const float* pq     = (const float*)d_in[1];
    const float* Wq     = (const float*)d_in[2];
    const float* bq     = (const float*)d_in[3];
    const float* Wk     = (const float*)d_in[4];
    const float* Wv     = (const float*)d_in[6];
    const float* bv     = (const float*)d_in[7];
    const float* Wp     = (const float*)d_in[8];
    const float* bp     = (const float*)d_in[9];
    const float* pds    = (const float*)d_in[10];
    const float* lnw    = (const float*)d_in[11];
    const float* lnb    = (const float*)d_in[12];

    float* pooled   = (float*)d_out;                       // [8,1,768]
    float* out_attn = (float*)d_out + BATCH * HIDDEN;      // [8,12,1,4096]

    const int k3_smem = K3_SMEM_FLOATS * sizeof(float);    // 59392 B
    static int s_attr_done = 0;
    if (!s_attr_done) {
        cudaFuncSetAttribute(k3_logits, cudaFuncAttributeMaxDynamicSharedMemorySize,
                             k3_smem);
        s_attr_done = 1;
    }

    k1_qpart  <<<288, 256>>>(pq, Wq);
    k1b_qscale<<<12, 256>>>(pds, bq);
    k2_fold   <<<1152, 256>>>(Wk);
    k3_logits <<<2048, 256, k3_smem>>>(hidden);
    k4_softmax<<<96, 1024>>>(out_attn, bv, bp);
    k5_pool   <<<512, 192>>>(hidden, out_attn);
    k6a_ctx   <<<192, 256>>>(Wv);
    k6b_out   <<<144, 256>>>(Wp);
    k7_ln     <<<8, 256>>>(pooled, lnw, lnb);
}

// round 16
// speedup vs baseline: 1.3123x; 1.0133x over previous
#include <cuda_runtime.h>
#include <math.h>

#define HIDDEN 768
#define INTER 3072
#define HEADS 12
#define HEAD_DIM 256
#define BATCH 8
#define SEQ 4096
#define K3_CHUNKS 4
#define K3_COLS 192
#define K3_TROWS 64
#define K3_PITCH 196          /* 192 + 4 pad; 784B stride, bank-safe */
#define K3_SMEM_FLOATS (K3_TROWS * K3_PITCH + K3_COLS * HEADS)
#define K5_CHUNKS 64
#define K5_ROWS 64
#define NLOGITS (BATCH * HEADS * SEQ)

typedef unsigned long long u64;

// ---------------- f32x2 helpers (sm_103a packed FMA) ----------------
__device__ __forceinline__ u64 pack2(float lo, float hi) {
    u64 r;
    asm("mov.b64 %0, {%1, %2};" : "=l"(r)
        : "r"(__float_as_uint(lo)), "r"(__float_as_uint(hi)));
    return r;
}
__device__ __forceinline__ void fma2(u64& d, u64 a, u64 b) {
    asm("fma.rn.f32x2 %0, %1, %2, %0;" : "+l"(d) : "l"(a), "l"(b));
}
__device__ __forceinline__ float2 unpack2(u64 v) {
    unsigned lo, hi;
    asm("mov.b64 {%0, %1}, %2;" : "=r"(lo), "=r"(hi) : "l"(v));
    return make_float2(__uint_as_float(lo), __uint_as_float(hi));
}

// ---------------- scratch (static device globals; no allocation) ----------------
__device__ float g_q1[24 * INTER];         // q partials per c-chunk
__device__ float g_q[INTER];               // scaled q [h][d]
__device__ float g_wk[HIDDEN * HEADS];     // folded key weights [c][h]
__device__ float g_logits[NLOGITS];        // logits (atomic-accumulated by k3)
__device__ float g_pp[BATCH * K5_CHUNKS * HEADS * HIDDEN]; // pool partials (18.9 MB)
__device__ float g_ctx[BATCH * INTER];
__device__ float g_out[BATCH * HIDDEN];    // pre-LN output

// ---------------- K1: q partials + zero g_logits ------------------------------
__global__ __launch_bounds__(256) void k1_qpart(const float* __restrict__ pq,
                                                const float* __restrict__ Wq) {
    int gid = blockIdx.x * 256 + threadIdx.x;       // 288*256 = 73728 threads
    for (int i = gid; i < NLOGITS; i += 288 * 256) g_logits[i] = 0.0f;

    int cc = blockIdx.x / 12;                       // 0..23
    int colc = blockIdx.x % 12;                     // 0..11
    int c0 = cc * 32;
    __shared__ float sq[32];
    if (threadIdx.x < 32) sq[threadIdx.x] = pq[c0 + threadIdx.x];
    __syncthreads();
    int col = colc * 256 + threadIdx.x;
    float acc = 0.0f;
#pragma unroll 8
    for (int c = 0; c < 32; c++)
        acc += sq[c] * Wq[(size_t)(c0 + c) * INTER + col];
    g_q1[cc * INTER + col] = acc;
}

// ---------------- K1b: reduce partials + bq, scale by softplus ------------------
__global__ void k1b_qscale(const float* __restrict__ pds,
                           const float* __restrict__ bq) {
    int i = blockIdx.x * 256 + threadIdx.x;         // grid 12*256 = 3072
    float s = bq[i];
#pragma unroll
    for (int cc = 0; cc < 24; cc++) s += g_q1[cc * INTER + i];
    float x = pds[threadIdx.x];                     // HEAD_DIM == 256
    float sp = (x > 20.0f) ? x : log1pf(expf(x));
    const float scale = 1.442695041f / 16.0f;       // r_softplus_0 / sqrt(HEAD_DIM)
    g_q[i] = s * scale * sp;
}

// ---------------- K2: fold wk[c][h] = Wk[c, h*256+:] . q[h,:] -------------------
// warp-per-(c,h): 9216 dot products. grid 1152 x 256. (q.bk dropped: softmax-invariant)
__global__ __launch_bounds__(256) void k2_fold(const float* __restrict__ Wk) {
    int p = blockIdx.x * 8 + (threadIdx.x >> 5);
    int lane = threadIdx.x & 31;
    int c = p / HEADS;
    int h = p - c * HEADS;
    const float* wrow = Wk + (size_t)c * INTER + h * HEAD_DIM;
    const float* qrow = g_q + h * HEAD_DIM;
    float s = 0.0f;
#pragma unroll
    for (int j = 0; j < HEAD_DIM; j += 32) s += wrow[j + lane] * qrow[j + lane];
#pragma unroll
    for (int o = 16; o; o >>= 1) s += __shfl_xor_sync(0xffffffffu, s, o);
    if (!lane) g_wk[p] = s;
}

// ---------------- K3: logit partials; 64-row tiles (R9 shape), atomic output ----
// grid = 512 rowblocks x 4 chunks = 2048; block 256; dynamic smem 58 KB.
__global__ __launch_bounds__(256) void k3_logits(const float* __restrict__ hidden) {
    extern __shared__ __align__(16) float dsm[];
    float* s_h  = dsm;                               // 64*196 = 12544 floats
    float* s_wk = dsm + K3_TROWS * K3_PITCH;         // 192*12 = 2304 floats
    float* s_red = dsm;                              // aliased after compute (6144)
    int chunk = blockIdx.x & 3;
    int rowblk = blockIdx.x >> 2;
    int row0 = rowblk * K3_TROWS;
    int tid = threadIdx.x;

    for (int i = tid; i < K3_COLS * HEADS; i += 256)
        s_wk[i] = g_wk[chunk * K3_COLS * HEADS + i];

    // stage 64 rows x 192 cols: r = tid>>2, sub = tid&3; 12 float4 each
    {
        int r = tid >> 2, sub = tid & 3;
        const float4* src = (const float4*)(hidden + (size_t)(row0 + r) * HIDDEN
                                            + chunk * K3_COLS);
        float4* dst = (float4*)(s_h + r * K3_PITCH);
#pragma unroll
        for (int j = 0; j < 12; j++)
            dst[sub + 4 * j] = src[sub + 4 * j];
    }
    __syncthreads();

    int w = tid >> 5, lane = tid & 31;
    const float* h0 = s_h + lane * K3_PITCH + w * 24;
    const float* h1 = h0 + 32 * K3_PITCH;
    const float* wks = s_wk + (w * 24) * HEADS;

    u64 acc0[6], acc1[6];
#pragma unroll
    for (int k = 0; k < 6; k++) { acc0[k] = 0ull; acc1[k] = 0ull; }

#pragma unroll
    for (int i = 0; i < 6; i++) {                   // 6 float4 = 24 cols
        float4 va = *(const float4*)(h0 + 4 * i);
        float4 vb = *(const float4*)(h1 + 4 * i);
        const ulonglong2* w2 = (const ulonglong2*)(wks + (4 * i) * HEADS);
        float aa[4] = {va.x, va.y, va.z, va.w};
        float bb[4] = {vb.x, vb.y, vb.z, vb.w};
#pragma unroll
        for (int j = 0; j < 4; j++) {
            ulonglong2 wa = w2[j * 3 + 0];
            ulonglong2 wb = w2[j * 3 + 1];
            ulonglong2 wc = w2[j * 3 + 2];
            u64 fa = pack2(aa[j], aa[j]);
            u64 fb = pack2(bb[j], bb[j]);
            fma2(acc0[0], fa, wa.x);
            fma2(acc0[1], fa, wa.y);
            fma2(acc0[2], fa, wb.x);
            fma2(acc0[3], fa, wb.y);
            fma2(acc0[4], fa, wc.x);
            fma2(acc0[5], fa, wc.y);
            fma2(acc1[0], fb, wa.x);
            fma2(acc1[1], fb, wa.y);
            fma2(acc1[2], fb, wb.x);
            fma2(acc1[3], fb, wb.y);
            fma2(acc1[4], fb, wc.x);
            fma2(acc1[5], fb, wc.y);
        }
    }
    __syncthreads();                                // all s_h reads done (aliasing)
    // per-warp partials -> s_red [w][row][head]
    {
        float* rp0 = s_red + (w * K3_TROWS + lane) * HEADS;
        float* rp1 = s_red + (w * K3_TROWS + lane + 32) * HEADS;
#pragma unroll
        for (int k = 0; k < 6; k++) {
            float2 p0 = unpack2(acc0[k]);
            float2 p1 = unpack2(acc1[k]);
            rp0[2 * k] = p0.x; rp0[2 * k + 1] = p0.y;
            rp1[2 * k] = p1.x; rp1[2 * k + 1] = p1.y;
        }
    }
    __syncthreads();
    // final reduce over 8 warps: 768 outputs, strided; atomic into g_logits
    for (int o = tid; o < K3_TROWS * HEADS; o += 256) {
        int rr = o / HEADS, h = o - rr * HEADS;
        float s = 0.0f;
#pragma unroll
        for (int ww = 0; ww < 8; ww++)
            s += s_red[(ww * K3_TROWS + rr) * HEADS + h];
        int grow = row0 + rr;
        int b = grow >> 12;
        int sq = grow & (SEQ - 1);
        atomicAdd(&g_logits[((size_t)(b * HEADS + h)) * SEQ + sq], s);
    }
}

// ---------------- K4: softmax over s per (b,h); 1024 thr for latency hiding -----
__global__ __launch_bounds__(1024) void k4_softmax(float* __restrict__ out_attn,
                                                   const float* __restrict__ bv,
                                                   const float* __restrict__ bp) {
    int gid = blockIdx.x * 1024 + threadIdx.x;      // grid 96 x 1024
    if (gid < BATCH * INTER) g_ctx[gid] = bv[gid % INTER];
    if (gid < BATCH * HIDDEN) g_out[gid] = bp[gid % HIDDEN];

    __shared__ float sv[SEQ];                       // 16 KB
    __shared__ float red[32];
    __shared__ float sbc;
    int bh = blockIdx.x;
    int tid = threadIdx.x, lane = tid & 31, wid = tid >> 5;
    size_t base = (size_t)bh * SEQ;

    float mx = -3.4e38f;
#pragma unroll
    for (int i = tid; i < SEQ; i += 1024) {
        float v = g_logits[base + i];
        sv[i] = v; mx = fmaxf(mx, v);
    }
#pragma unroll
    for (int o = 16; o; o >>= 1) mx = fmaxf(mx, __shfl_xor_sync(0xffffffffu, mx, o));
    if (!lane) red[wid] = mx;
    __syncthreads();
    if (tid == 0) { float m = red[0]; for (int w = 1; w < 32; w++) m = fmaxf(m, red[w]); sbc = m; }
    __syncthreads();
    float m = sbc;

    float sum = 0.0f;
#pragma unroll
    for (int i = tid; i < SEQ; i += 1024) { float e = __expf(sv[i] - m); sv[i] = e; sum += e; }
#pragma unroll
    for (int o = 16; o; o >>= 1) sum += __shfl_xor_sync(0xffffffffu, sum, o);
    if (!lane) red[wid] = sum;
    __syncthreads();
    if (tid == 0) { float s = 0; for (int w = 0; w < 32; w++) s += red[w]; sbc = 1.0f / s; }
    __syncthreads();
    float inv = sbc;
#pragma unroll
    for (int i = tid; i < SEQ; i += 1024) out_attn[base + i] = sv[i] * inv;
}

// ---------------- K5: partial p[b,h,c] = sum_s attn * hidden (pass C) -----------
// grid = 8 b x 64 chunks = 512; block 384 (12 warps); thread owns 2 floats.
// Halved accumulator state -> more resident warps for latency hiding.
__global__ __launch_bounds__(384) void k5_pool(const float* __restrict__ hidden,
                                               const float* __restrict__ attn) {
    __shared__ __align__(16) float s_a[K5_ROWS * HEADS]; // [r][h], 3 KB
    int b = blockIdx.x >> 6;
    int s0 = (blockIdx.x & (K5_CHUNKS - 1)) * K5_ROWS;
    for (int i = threadIdx.x; i < K5_ROWS * HEADS; i += 384) {
        int h = i / K5_ROWS, r = i - h * K5_ROWS;   // coalesced attn reads
        s_a[r * HEADS + h] = attn[((size_t)(b * HEADS + h)) * SEQ + s0 + r];
    }
    __syncthreads();

    int c0 = threadIdx.x * 2;                       // 384*2 = 768
    const float2* hp = (const float2*)(hidden + ((size_t)b * SEQ + s0) * HIDDEN)
                     + threadIdx.x;

    u64 acc[6][2];                                  // [head-pair][col]
#pragma unroll
    for (int k = 0; k < 6; k++) { acc[k][0] = 0ull; acc[k][1] = 0ull; }

#pragma unroll 8
    for (int r = 0; r < K5_ROWS; r++) {
        float2 hv = hp[(size_t)r * (HIDDEN / 2)];
        u64 hx = pack2(hv.x, hv.x);
        u64 hy = pack2(hv.y, hv.y);
        const ulonglong2* ap = (const ulonglong2*)(s_a + r * HEADS);
        ulonglong2 a0 = ap[0], a1 = ap[1], a2 = ap[2];
        u64 av[6] = {a0.x, a0.y, a1.x, a1.y, a2.x, a2.y};
#pragma unroll
        for (int k = 0; k < 6; k++) {
            fma2(acc[k][0], av[k], hx);
            fma2(acc[k][1], av[k], hy);
        }
    }
    float* pp = g_pp + (size_t)blockIdx.x * (HEADS * HIDDEN);
#pragma unroll
    for (int k = 0; k < 6; k++) {
        float2 p0 = unpack2(acc[k][0]);             // (head 2k, 2k+1) col c0
        float2 p1 = unpack2(acc[k][1]);             // (head 2k, 2k+1) col c0+1
        *(float2*)(pp + (2 * k) * HIDDEN + c0)     = make_float2(p0.x, p1.x);
        *(float2*)(pp + (2 * k + 1) * HIDDEN + c0) = make_float2(p0.y, p1.y);
    }
}

// ---------------- K6a: ctx = (chunk-reduced p) @ Wv cols + bv (atomic over c) ---
__global__ __launch_bounds__(256) void k6a_ctx(const float* __restrict__ Wv) {
    int h = blockIdx.x >> 4;                        // grid 12*16
    int c0 = (blockIdx.x & 15) * 48;
    __shared__ float sp[BATCH][48];
    for (int i = threadIdx.x; i < BATCH * 48; i += 256) {
        int b = i / 48, c = i - b * 48;
        const float* src = g_pp + (size_t)(b * K5_CHUNKS) * (HEADS * HIDDEN)
                         + h * HIDDEN + c0 + c;
        float s = 0.0f;
#pragma unroll 8
        for (int ch = 0; ch < K5_CHUNKS; ch++)
            s += src[(size_t)ch * (HEADS * HIDDEN)];
        sp[b][c] = s;
    }
    __syncthreads();
    int col = h * HEAD_DIM + threadIdx.x;
    float acc[BATCH];
#pragma unroll
    for (int b = 0; b < BATCH; b++) acc[b] = 0.0f;
#pragma unroll 4
    for (int c = 0; c < 48; c++) {
        float w = Wv[(size_t)(c0 + c) * INTER + col];
#pragma unroll
        for (int b = 0; b < BATCH; b++) acc[b] += sp[b][c] * w;
    }
#pragma unroll
    for (int b = 0; b < BATCH; b++) atomicAdd(&g_ctx[b * INTER + col], acc[b]);
}

// ---------------- K6b: out[b,j] = ctx[b,:].Wp col + bp (atomic over i) -----------
__global__ __launch_bounds__(256) void k6b_out(const float* __restrict__ Wp) {
    int ic = blockIdx.x / 3;                        // grid 48*3
    int jt = blockIdx.x % 3;
    int i0 = ic * 64;
    __shared__ float sc[BATCH][64];
    for (int i = threadIdx.x; i < BATCH * 64; i += 256) {
        int b = i / 64, ii = i - b * 64;
        sc[b][ii] = g_ctx[b * INTER + i0 + ii];
    }
    __syncthreads();
    int j = jt * 256 + threadIdx.x;
    float acc[BATCH];
#pragma unroll
    for (int b = 0; b < BATCH; b++) acc[b] = 0.0f;
#pragma unroll 4
    for (int ii = 0; ii < 64; ii++) {
        float w = Wp[(size_t)(i0 + ii) * HIDDEN + j];
#pragma unroll
        for (int b = 0; b < BATCH; b++) acc[b] += sc[b][ii] * w;
    }
#pragma unroll
    for (int b = 0; b < BATCH; b++) atomicAdd(&g_out[b * HIDDEN + j], acc[b]);
}

// ---------------- K7: layernorm per batch row -> pooled output -------------------
__global__ __launch_bounds__(256) void k7_ln(float* __restrict__ pooled,
                                             const float* __restrict__ lnw,
                                             const float* __restrict__ lnb) {
    int b = blockIdx.x, tid = threadIdx.x, lane = tid & 31, wid = tid >> 5;
    __shared__ float sx[HIDDEN];
    __shared__ float red[8];
    __shared__ float sm, sr;
    float loc = 0.0f;
    for (int i = tid; i < HIDDEN; i += 256) { float x = g_out[b * HIDDEN + i]; sx[i] = x; loc += x; }
#pragma unroll
    for (int o = 16; o; o >>= 1) loc += __shfl_xor_sync(0xffffffffu, loc, o);
    if (!lane) red[wid] = loc;
    __syncthreads();
    if (tid == 0) { float s = 0; for (int w = 0; w < 8; w++) s += red[w]; sm = s / HIDDEN; }
    __syncthreads();
    float mean = sm;
    loc = 0.0f;
    for (int i = tid; i < HIDDEN; i += 256) { float d = sx[i] - mean; loc += d * d; }
#pragma unroll
    for (int o = 16; o; o >>= 1) loc += __shfl_xor_sync(0xffffffffu, loc, o);
    if (!lane) red[wid] = loc;
    __syncthreads();
    if (tid == 0) { float s = 0; for (int w = 0; w < 8; w++) s += red[w]; sr = rsqrtf(s / HIDDEN + 1e-6f); }
    __syncthreads();
    float rstd = sr;
    for (int i = tid; i < HIDDEN; i += 256)
        pooled[b * HIDDEN + i] = (sx[i] - mean) * rstd * (lnw[i] + 1.0f) + lnb[i];
}

// ---------------- launch -----------------------------------------------------------
extern "C" void kernel_launch(void* const* d_in, const int* in_sizes, int n_in,
                              void* d_out, int out_size) {
    const float* hidden = (const float*)d_in[0];
    const float* pq     = (const float*)d_in[1];
    const float* Wq     = (const float*)d_in[2];
    const float* bq     = (const float*)d_in[3];
    const float* Wk     = (const float*)d_in[4];
    const float* Wv     = (const float*)d_in[6];
    const float* bv     = (const float*)d_in[7];
    const float* Wp     = (const float*)d_in[8];
    const float* bp     = (const float*)d_in[9];
    const float* pds    = (const float*)d_in[10];
    const float* lnw    = (const float*)d_in[11];
    const float* lnb    = (const float*)d_in[12];

    float* pooled   = (float*)d_out;                       // [8,1,768]
    float* out_attn = (float*)d_out + BATCH * HIDDEN;      // [8,12,1,4096]

    const int k3_smem = K3_SMEM_FLOATS * sizeof(float);    // 59392 B
    static int s_attr_done = 0;
    if (!s_attr_done) {
        cudaFuncSetAttribute(k3_logits, cudaFuncAttributeMaxDynamicSharedMemorySize,
                             k3_smem);
        s_attr_done = 1;
    }

    k1_qpart  <<<288, 256>>>(pq, Wq);
    k1b_qscale<<<12, 256>>>(pds, bq);
    k2_fold   <<<1152, 256>>>(Wk);
    k3_logits <<<2048, 256, k3_smem>>>(hidden);
    k4_softmax<<<96, 1024>>>(out_attn, bv, bp);
    k5_pool   <<<512, 384>>>(hidden, out_attn);
    k6a_ctx   <<<192, 256>>>(Wv);
    k6b_out   <<<144, 256>>>(Wp);
    k7_ln     <<<8, 256>>>(pooled, lnw, lnb);
}